// round 12
// baseline (speedup 1.0000x reference)
#include <cuda_runtime.h>
#include <cuda_bf16.h>
#include <cstdint>

#define KC 128
#define DD 128
#define TM 64
#define TPB 256
#define NCTA 592

// ---- device scratch ----
__device__ float g_acc[KC];
__device__ float g_masksum;
__device__ int   g_count;

// ---- smem layout (bytes) ----
#define SM_A    0                 // 64*256  = 16384 (X bf16, swizzled)
#define SM_B    16384             // 128*256 = 32768 (C bf16, swizzled)
#define SM_X2   49152             // 256
#define SM_MS   49408             // 256
#define SM_C2   49664             // 512
#define SM_IC   50176             // 512
#define SM_SCOL 50688             // 512
#define SM_MSUM 51200             // 4
#define SM_FLAG 51204             // 4
#define SM_TOTAL 51208            // x4 CTAs = 204.8 KB

__device__ __forceinline__ uint32_t smem_u32(const void* p) {
    uint32_t a;
    asm("{ .reg .u64 t; cvta.to.shared.u64 t, %1; cvt.u32.u64 %0, t; }" : "=r"(a) : "l"(p));
    return a;
}
__device__ __forceinline__ uint32_t bf2u(__nv_bfloat162 h) {
    return *reinterpret_cast<uint32_t*>(&h);
}
__device__ __forceinline__ void ldsm4(uint32_t& r0, uint32_t& r1, uint32_t& r2, uint32_t& r3,
                                      uint32_t addr) {
    asm volatile("ldmatrix.sync.aligned.m8n8.x4.shared.b16 {%0,%1,%2,%3}, [%4];"
                 : "=r"(r0), "=r"(r1), "=r"(r2), "=r"(r3) : "r"(addr));
}
__device__ __forceinline__ void mma16816(float* c, const uint32_t* a, const uint32_t* b) {
    asm volatile(
        "mma.sync.aligned.m16n8k16.row.col.f32.bf16.bf16.f32 "
        "{%0,%1,%2,%3}, {%4,%5,%6,%7}, {%8,%9}, {%0,%1,%2,%3};"
        : "+f"(c[0]), "+f"(c[1]), "+f"(c[2]), "+f"(c[3])
        : "r"(a[0]), "r"(a[1]), "r"(a[2]), "r"(a[3]), "r"(b[0]), "r"(b[1]));
}
__device__ __forceinline__ float sqrt_ap(float v) {
    float r; asm("sqrt.approx.f32 %0, %1;" : "=f"(r) : "f"(v)); return r;
}
__device__ __forceinline__ float lg2_ap(float v) {
    float r; asm("lg2.approx.f32 %0, %1;" : "=f"(r) : "f"(v)); return r;
}
__device__ __forceinline__ float rcp_ap(float v) {
    float r; asm("rcp.approx.f32 %0, %1;" : "=f"(r) : "f"(v)); return r;
}
// d = dot, xc = x2+c2, R = 2*rcp(1-x2)*rcp(1-c2), lm = ln2*mask
__device__ __forceinline__ float pdist(float d, float xc, float R, float lm) {
    float sq  = fmaxf(fmaf(d, -2.0f, xc), 0.0f);
    float arg = fmaxf(fmaf(sq, R, 1.0f), 1.0f + 1e-7f);
    float v   = arg + sqrt_ap(fmaf(arg, arg, -1.0f));
    return lg2_ap(v) * lm;
}

__global__ void __launch_bounds__(TPB, 4)
dist_kernel(const float* __restrict__ x,
            const float* __restrict__ mask,
            const float* __restrict__ cw,
            float* __restrict__ out, int N, int ntiles) {
    extern __shared__ char smem[];
    const uint32_t sb = smem_u32(smem);
    const int tid = threadIdx.x, wid = tid >> 5, l = tid & 31;
    const int wr = wid & 1, wc = wid >> 1;    // warp grid 2 (rows) x 4 (cols)

    float* x2s  = (float*)(smem + SM_X2);
    float* ms   = (float*)(smem + SM_MS);
    float* c2s  = (float*)(smem + SM_C2);
    float* ics  = (float*)(smem + SM_IC);
    float* scol = (float*)(smem + SM_SCOL);
    float* msum = (float*)(smem + SM_MSUM);
    int*   flag = (int*)(smem + SM_FLAG);
    float* out_node = out + KC;

    // ---- inline centroid prep: 8 warps x 16 rows ----
#pragma unroll 2
    for (int r16 = 0; r16 < 16; r16++) {
        int row = wid * 16 + r16;
        float4 v = ((const float4*)(cw + (size_t)row * DD))[l];
        float ss = v.x * v.x + v.y * v.y + v.z * v.z + v.w * v.w;
#pragma unroll
        for (int o = 16; o; o >>= 1) ss += __shfl_xor_sync(0xffffffffu, ss, o);
        float norm = fmaxf(sqrtf(ss), 1e-5f);
        float s = tanhf(fminf(norm, 15.0f)) / norm;
        uint2 st;
        st.x = bf2u(__float22bfloat162_rn(make_float2(v.x * s, v.y * s)));
        st.y = bf2u(__float22bfloat162_rn(make_float2(v.z * s, v.w * s)));
        int c = l >> 1, half = l & 1;
        *(uint2*)(smem + SM_B + row * 256 + (((c ^ (row & 7)) << 4) | (half << 3))) = st;
        if (l == 0) {
            float c2 = ss * s * s;
            c2s[row] = c2;
            ics[row] = 2.0f / (1.0f - c2);
        }
    }
    if (tid < KC) scol[tid] = 0.0f;
    if (tid == 0) *msum = 0.0f;
    __syncthreads();

    const int a_row0 = wr * 32 + (l & 15);
    const int a_hi   = l >> 4;
    const int b_off  = ((l >> 4) << 3) + (l & 7);
    const int b_hi   = (l >> 3) & 1;

    for (int tile = blockIdx.x; tile < ntiles; tile += NCTA) {
        const int tile0 = tile * TM;

        // ---- convert: LDG fp32 -> exact x2 + bf16 A tile (swizzled) ----
#pragma unroll
        for (int j = 0; j < 8; j++) {
            int i = tid + TPB * j;            // one row per warp per j
            int row = i >> 5, c = i & 31;
            int gr = tile0 + row; if (gr >= N) gr = N - 1;
            float4 v = ((const float4*)x)[(size_t)gr * 32 + c];
            float ss = v.x * v.x + v.y * v.y + v.z * v.z + v.w * v.w;
#pragma unroll
            for (int o = 16; o; o >>= 1) ss += __shfl_xor_sync(0xffffffffu, ss, o);
            if (l == 0) x2s[row] = ss;
            uint2 st;
            st.x = bf2u(__float22bfloat162_rn(make_float2(v.x, v.y)));
            st.y = bf2u(__float22bfloat162_rn(make_float2(v.z, v.w)));
            *(uint2*)(smem + SM_A + row * 256 +
                      ((((c >> 1) ^ (row & 7)) << 4) | ((c & 1) << 3))) = st;
        }
        if (tid < TM) {
            int gr = tile0 + tid;
            ms[tid] = (gr < N) ? mask[gr] : 0.0f;
        }
        __syncthreads();

        if (wid == 0) {
            float wm = ms[l] + ms[l + 32];
#pragma unroll
            for (int o = 16; o; o >>= 1) wm += __shfl_xor_sync(0xffffffffu, wm, o);
            if (l == 0) *msum += wm;
        }

        // ---- two column passes: warp tile 32 rows x 16 cols ----
#pragma unroll 1
        for (int pass = 0; pass < 2; pass++) {
            float acc[2][2][4];
#pragma unroll
            for (int mi = 0; mi < 2; mi++)
#pragma unroll
                for (int t = 0; t < 2; t++)
#pragma unroll
                    for (int u = 0; u < 4; u++) acc[mi][t][u] = 0.0f;

            const int nrow = pass * 64 + wc * 16 + b_off;
            const uint32_t bd0 = sb + SM_B + nrow * 256;

#pragma unroll
            for (int kk = 0; kk < 8; kk++) {
                uint32_t bfr[4];                // B frag first (low live-reg window)
                ldsm4(bfr[0], bfr[1], bfr[2], bfr[3],
                      bd0 + ((((kk << 1) | b_hi) ^ (nrow & 7)) << 4));
#pragma unroll
                for (int mi = 0; mi < 2; mi++) {
                    uint32_t af[4];
                    int row = a_row0 + mi * 16;
                    ldsm4(af[0], af[1], af[2], af[3],
                          sb + SM_A + row * 256 + ((((kk << 1) | a_hi) ^ (row & 7)) << 4));
                    mma16816(acc[mi][0], af, bfr);
                    mma16816(acc[mi][1], af, bfr + 2);
                }
            }

            // epilogue: one output row at a time (minimal live state)
            float cs0 = 0.0f, cs1 = 0.0f, cs2 = 0.0f, cs3 = 0.0f;
#pragma unroll
            for (int mi = 0; mi < 2; mi++) {
#pragma unroll
                for (int rr = 0; rr < 2; rr++) {
                    int r = wr * 32 + mi * 16 + rr * 8 + (l >> 2);
                    float lm = ms[r] * 0.69314718f;
                    float x2 = x2s[r];
                    float ri = rcp_ap(1.0f - x2);
                    int gr = tile0 + r;
                    float* pr = out_node + (size_t)gr * KC;
                    int col0 = pass * 64 + wc * 16 + ((l & 3) << 1);
                    float d0 = pdist(acc[mi][0][rr * 2],     x2 + c2s[col0],
                                     ri * ics[col0],     lm);
                    float d1 = pdist(acc[mi][0][rr * 2 + 1], x2 + c2s[col0 + 1],
                                     ri * ics[col0 + 1], lm);
                    float d2 = pdist(acc[mi][1][rr * 2],     x2 + c2s[col0 + 8],
                                     ri * ics[col0 + 8], lm);
                    float d3 = pdist(acc[mi][1][rr * 2 + 1], x2 + c2s[col0 + 9],
                                     ri * ics[col0 + 9], lm);
                    if (gr < N) {
                        *(float2*)(pr + col0)     = make_float2(d0, d1);
                        *(float2*)(pr + col0 + 8) = make_float2(d2, d3);
                    }
                    cs0 += d0; cs1 += d1; cs2 += d2; cs3 += d3;
                }
            }
#pragma unroll
            for (int o = 4; o <= 16; o <<= 1) {
                cs0 += __shfl_xor_sync(0xffffffffu, cs0, o);
                cs1 += __shfl_xor_sync(0xffffffffu, cs1, o);
                cs2 += __shfl_xor_sync(0xffffffffu, cs2, o);
                cs3 += __shfl_xor_sync(0xffffffffu, cs3, o);
            }
            if (l < 4) {
                int col0 = pass * 64 + wc * 16 + ((l & 3) << 1);
                atomicAdd(&scol[col0],     cs0);
                atomicAdd(&scol[col0 + 1], cs1);
                atomicAdd(&scol[col0 + 8], cs2);
                atomicAdd(&scol[col0 + 9], cs3);
            }
        }
        __syncthreads();   // protect A/ms/x2s before next tile's convert
    }

    // ---- flush partials ----
    if (tid < KC) atomicAdd(&g_acc[tid], scol[tid]);
    if (tid == 0) atomicAdd(&g_masksum, *msum);
    __threadfence();
    __syncthreads();
    if (tid == 0) {
        int old = atomicAdd(&g_count, 1);
        *flag = (old == NCTA - 1) ? 1 : 0;
    }
    __syncthreads();
    if (*flag) {
        __threadfence();
        if (tid < KC) {
            float s  = atomicAdd(&g_acc[tid], 0.0f);      // coherent read
            float tm = atomicAdd(&g_masksum, 0.0f);
            out[tid] = s / tm;
        }
        __syncthreads();
        if (tid < KC) g_acc[tid] = 0.0f;                  // reset for next replay
        if (tid == 0) { g_masksum = 0.0f; atomicExch(&g_count, 0); }
    }
}

extern "C" void kernel_launch(void* const* d_in, const int* in_sizes, int n_in,
                              void* d_out, int out_size) {
    const float* x    = (const float*)d_in[0];
    const float* mask = (const float*)d_in[1];
    const float* cw   = (const float*)d_in[2];
    const int N = in_sizes[1];
    float* out = (float*)d_out;

    cudaFuncSetAttribute(dist_kernel, cudaFuncAttributeMaxDynamicSharedMemorySize, SM_TOTAL);
    const int ntiles = (N + TM - 1) / TM;
    dist_kernel<<<NCTA, TPB, SM_TOTAL>>>(x, mask, cw, out, N, ntiles);
}

// round 13
// speedup vs baseline: 1.1365x; 1.1365x over previous
#include <cuda_runtime.h>
#include <cuda_bf16.h>
#include <cstdint>

#define KC 128
#define DD 128
#define TM 64
#define TPB 256
#define NCTA 456

// ---- device scratch ----
__device__ float g_acc[KC];
__device__ float g_masksum;
__device__ int   g_count;

// ---- smem layout (bytes) ----
#define SM_A    0                 // 16384 (X bf16, swizzled)
#define SM_B    16384             // 32768 (C bf16, swizzled)
#define SM_PX2  49152             // 8192  (x2 partials [64][32] f32)
#define SM_X2   57344             // 256
#define SM_MS   57600             // 256
#define SM_C2   57856             // 512
#define SM_IC   58368             // 512
#define SM_SCOL 58880             // 512
#define SM_FLAG 59392             // 4
#define SM_TOTAL 59400            // x3 CTAs = 178 KB

__device__ __forceinline__ uint32_t smem_u32(const void* p) {
    uint32_t a;
    asm("{ .reg .u64 t; cvta.to.shared.u64 t, %1; cvt.u32.u64 %0, t; }" : "=r"(a) : "l"(p));
    return a;
}
__device__ __forceinline__ uint32_t bf2u(__nv_bfloat162 h) {
    return *reinterpret_cast<uint32_t*>(&h);
}
__device__ __forceinline__ void ldsm4(uint32_t& r0, uint32_t& r1, uint32_t& r2, uint32_t& r3,
                                      uint32_t addr) {
    asm volatile("ldmatrix.sync.aligned.m8n8.x4.shared.b16 {%0,%1,%2,%3}, [%4];"
                 : "=r"(r0), "=r"(r1), "=r"(r2), "=r"(r3) : "r"(addr));
}
__device__ __forceinline__ void mma16816(float* c, const uint32_t* a, const uint32_t* b) {
    asm volatile(
        "mma.sync.aligned.m16n8k16.row.col.f32.bf16.bf16.f32 "
        "{%0,%1,%2,%3}, {%4,%5,%6,%7}, {%8,%9}, {%0,%1,%2,%3};"
        : "+f"(c[0]), "+f"(c[1]), "+f"(c[2]), "+f"(c[3])
        : "r"(a[0]), "r"(a[1]), "r"(a[2]), "r"(a[3]), "r"(b[0]), "r"(b[1]));
}
__device__ __forceinline__ float sqrt_ap(float v) {
    float r; asm("sqrt.approx.f32 %0, %1;" : "=f"(r) : "f"(v)); return r;
}
__device__ __forceinline__ float lg2_ap(float v) {
    float r; asm("lg2.approx.f32 %0, %1;" : "=f"(r) : "f"(v)); return r;
}
__device__ __forceinline__ float rcp_ap(float v) {
    float r; asm("rcp.approx.f32 %0, %1;" : "=f"(r) : "f"(v)); return r;
}
__device__ __forceinline__ float pdist(float d, float xc, float R, float lm) {
    float sq  = fmaxf(fmaf(d, -2.0f, xc), 0.0f);
    float arg = fmaxf(fmaf(sq, R, 1.0f), 1.0f + 1e-7f);
    float v   = arg + sqrt_ap(fmaf(arg, arg, -1.0f));
    return lg2_ap(v) * lm;
}

__global__ void __launch_bounds__(TPB, 3)
dist_kernel(const float* __restrict__ x,
            const float* __restrict__ mask,
            const float* __restrict__ cw,
            float* __restrict__ out, int N, int ntiles) {
    extern __shared__ char smem[];
    const uint32_t sb = smem_u32(smem);
    const int tid = threadIdx.x, wid = tid >> 5, l = tid & 31;
    const int wr = wid & 1, wc = wid >> 1;    // warp grid 2 (rows) x 4 (cols)

    float* x2s  = (float*)(smem + SM_X2);
    float* ms   = (float*)(smem + SM_MS);
    float* c2s  = (float*)(smem + SM_C2);
    float* ics  = (float*)(smem + SM_IC);
    float* scol = (float*)(smem + SM_SCOL);
    float* px2  = (float*)(smem + SM_PX2);
    int*   flag = (int*)(smem + SM_FLAG);
    float* out_node = out + KC;

    // ---- inline centroid prep: 8 warps x 16 rows ----
#pragma unroll 2
    for (int r16 = 0; r16 < 16; r16++) {
        int row = wid * 16 + r16;
        float4 v = ((const float4*)(cw + (size_t)row * DD))[l];
        float ss = v.x * v.x + v.y * v.y + v.z * v.z + v.w * v.w;
#pragma unroll
        for (int o = 16; o; o >>= 1) ss += __shfl_xor_sync(0xffffffffu, ss, o);
        float norm = fmaxf(sqrtf(ss), 1e-5f);
        float s = tanhf(fminf(norm, 15.0f)) / norm;
        uint2 st;
        st.x = bf2u(__float22bfloat162_rn(make_float2(v.x * s, v.y * s)));
        st.y = bf2u(__float22bfloat162_rn(make_float2(v.z * s, v.w * s)));
        int c = l >> 1, half = l & 1;
        *(uint2*)(smem + SM_B + row * 256 + (((c ^ (row & 7)) << 4) | (half << 3))) = st;
        if (l == 0) {
            float c2 = ss * s * s;
            c2s[row] = c2;
            ics[row] = 2.0f / (1.0f - c2);
        }
    }
    if (tid < KC) scol[tid] = 0.0f;
    __syncthreads();

    const int a_row0 = wr * 32 + (l & 15);
    const int a_hi   = l >> 4;
    const int b_off  = ((l >> 4) << 3) + (l & 7);
    const int b_hi   = (l >> 3) & 1;

    float cs[8];
#pragma unroll
    for (int v = 0; v < 8; v++) cs[v] = 0.0f;
    float msacc = 0.0f;

    for (int tile = blockIdx.x; tile < ntiles; tile += NCTA) {
        const int tile0 = tile * TM;

        // ---- convert: LDG fp32 -> bf16 A tile (swizzled) + x2 partial STS ----
#pragma unroll
        for (int j = 0; j < 8; j++) {
            int i = tid + TPB * j;            // row = warp-uniform, c == lane
            int row = i >> 5, c = i & 31;
            int gr = tile0 + row; if (gr >= N) gr = N - 1;
            float4 v = ((const float4*)x)[(size_t)gr * 32 + c];
            px2[row * 32 + c] = v.x * v.x + v.y * v.y + v.z * v.z + v.w * v.w;
            uint2 st;
            st.x = bf2u(__float22bfloat162_rn(make_float2(v.x, v.y)));
            st.y = bf2u(__float22bfloat162_rn(make_float2(v.z, v.w)));
            *(uint2*)(smem + SM_A + row * 256 +
                      ((((c >> 1) ^ (row & 7)) << 4) | ((c & 1) << 3))) = st;
        }
        if (tid < TM) {
            int gr = tile0 + tid;
            float mv = (gr < N) ? mask[gr] : 0.0f;
            ms[tid] = mv;
            msacc += mv;
        }
        __syncthreads();

        // ---- phase 2: x2 row sums (4 threads/row, 2 shfl) ----
        {
            int row = tid >> 2, q = tid & 3;
            const float4* pp = (const float4*)(smem + SM_PX2 + row * 128 + q * 32);
            float4 a = pp[0], b = pp[1];
            float s = ((a.x + a.y) + (a.z + a.w)) + ((b.x + b.y) + (b.z + b.w));
            s += __shfl_xor_sync(0xffffffffu, s, 1);
            s += __shfl_xor_sync(0xffffffffu, s, 2);
            if (q == 0) x2s[row] = s;
        }
        __syncthreads();

        // ---- two column passes: warp tile 32 rows x 16 cols ----
#pragma unroll 1
        for (int pass = 0; pass < 2; pass++) {
            float acc[2][2][4];
#pragma unroll
            for (int mi = 0; mi < 2; mi++)
#pragma unroll
                for (int t = 0; t < 2; t++)
#pragma unroll
                    for (int u = 0; u < 4; u++) acc[mi][t][u] = 0.0f;

            const int nrow = pass * 64 + wc * 16 + b_off;
            const uint32_t bd0 = sb + SM_B + nrow * 256;

#pragma unroll
            for (int kk = 0; kk < 8; kk++) {
                uint32_t af[2][4];
#pragma unroll
                for (int mi = 0; mi < 2; mi++) {
                    int row = a_row0 + mi * 16;
                    uint32_t ad = sb + SM_A + row * 256
                                + ((((kk << 1) | a_hi) ^ (row & 7)) << 4);
                    ldsm4(af[mi][0], af[mi][1], af[mi][2], af[mi][3], ad);
                }
                uint32_t bfr[2][2];
                {
                    uint32_t bdk = bd0 + ((((kk << 1) | b_hi) ^ (nrow & 7)) << 4);
                    uint32_t r0, r1, r2, r3;
                    ldsm4(r0, r1, r2, r3, bdk);
                    bfr[0][0] = r0; bfr[0][1] = r1;
                    bfr[1][0] = r2; bfr[1][1] = r3;
                }
#pragma unroll
                for (int mi = 0; mi < 2; mi++)
#pragma unroll
                    for (int t = 0; t < 2; t++) mma16816(acc[mi][t], af[mi], bfr[t]);
            }

            // epilogue: accumulate column sums in persistent registers
#pragma unroll
            for (int mi = 0; mi < 2; mi++) {
                int r0 = wr * 32 + mi * 16 + (l >> 2);
                int r1 = r0 + 8;
                float lm0 = ms[r0] * 0.69314718f, lm1 = ms[r1] * 0.69314718f;
                float x20 = x2s[r0], x21 = x2s[r1];
                float ri0 = rcp_ap(1.0f - x20), ri1 = rcp_ap(1.0f - x21);
                bool v0ok = (tile0 + r0) < N, v1ok = (tile0 + r1) < N;
                float* p0r = out_node + (size_t)(tile0 + r0) * KC;
                float* p1r = out_node + (size_t)(tile0 + r1) * KC;
#pragma unroll
                for (int t = 0; t < 2; t++) {
                    int col = pass * 64 + wc * 16 + t * 8 + ((l & 3) << 1);
                    float2 c2p = *(float2*)(c2s + col);
                    float2 icp = *(float2*)(ics + col);
                    float d0 = pdist(acc[mi][t][0], x20 + c2p.x, ri0 * icp.x, lm0);
                    float d1 = pdist(acc[mi][t][1], x20 + c2p.y, ri0 * icp.y, lm0);
                    float d2 = pdist(acc[mi][t][2], x21 + c2p.x, ri1 * icp.x, lm1);
                    float d3 = pdist(acc[mi][t][3], x21 + c2p.y, ri1 * icp.y, lm1);
                    if (v0ok) *(float2*)(p0r + col) = make_float2(d0, d1);
                    if (v1ok) *(float2*)(p1r + col) = make_float2(d2, d3);
                    cs[pass * 4 + t * 2]     += d0 + d2;
                    cs[pass * 4 + t * 2 + 1] += d1 + d3;
                }
            }
        }
        __syncthreads();   // protect A/px2/ms/x2s before next tile's convert
    }

    // ---- one-time column-sum reduction ----
#pragma unroll
    for (int v = 0; v < 8; v++) {
        float s = cs[v];
        s += __shfl_xor_sync(0xffffffffu, s, 4);
        s += __shfl_xor_sync(0xffffffffu, s, 8);
        s += __shfl_xor_sync(0xffffffffu, s, 16);
        if (l < 4) {
            int col = (v >> 2) * 64 + wc * 16 + ((v >> 1) & 1) * 8 + ((l & 3) << 1) + (v & 1);
            atomicAdd(&scol[col], s);
        }
    }
    {
        float wm = msacc;
#pragma unroll
        for (int o = 16; o; o >>= 1) wm += __shfl_xor_sync(0xffffffffu, wm, o);
        if (l == 0 && wm != 0.0f) atomicAdd(&g_masksum, wm);
        if (l == 0 && wid == 0 && wm == 0.0f && msacc != 0.0f)
            atomicAdd(&g_masksum, 0.0f);  // (unreachable; keeps compiler honest)
    }
    __syncthreads();

    // ---- flush partials ----
    if (tid < KC) atomicAdd(&g_acc[tid], scol[tid]);
    __threadfence();
    __syncthreads();
    if (tid == 0) {
        int old = atomicAdd(&g_count, 1);
        *flag = (old == NCTA - 1) ? 1 : 0;
    }
    __syncthreads();
    if (*flag) {
        __threadfence();
        if (tid < KC) {
            float s  = atomicAdd(&g_acc[tid], 0.0f);      // coherent read
            float tm = atomicAdd(&g_masksum, 0.0f);
            out[tid] = s / tm;
        }
        __syncthreads();
        if (tid < KC) g_acc[tid] = 0.0f;                  // reset for next replay
        if (tid == 0) { g_masksum = 0.0f; atomicExch(&g_count, 0); }
    }
}

extern "C" void kernel_launch(void* const* d_in, const int* in_sizes, int n_in,
                              void* d_out, int out_size) {
    const float* x    = (const float*)d_in[0];
    const float* mask = (const float*)d_in[1];
    const float* cw   = (const float*)d_in[2];
    const int N = in_sizes[1];
    float* out = (float*)d_out;

    cudaFuncSetAttribute(dist_kernel, cudaFuncAttributeMaxDynamicSharedMemorySize, SM_TOTAL);
    const int ntiles = (N + TM - 1) / TM;
    dist_kernel<<<NCTA, TPB, SM_TOTAL>>>(x, mask, cw, out, N, ntiles);
}

// round 15
// speedup vs baseline: 1.1415x; 1.0044x over previous
#include <cuda_runtime.h>
#include <cuda_bf16.h>
#include <cstdint>

#define KC 128
#define DD 128
#define TM 64
#define TPB 256
#define NCTA 456

// ---- device scratch ----
__device__ float g_acc[KC];
__device__ float g_masksum;
__device__ int   g_count;

// ---- smem layout (bytes) ----
#define SM_A    0                 // 16384 (X bf16, swizzled)
#define SM_B    16384             // 32768 (C bf16, swizzled)
#define SM_PX2  49152             // 8192  (x2 partials [64][32] f32)
#define SM_X2   57344             // 256
#define SM_RIS  57600             // 256  rcp(1-x2) per row
#define SM_LMS  57856             // 256  mask*ln2 per row
#define SM_MS   58112             // 256
#define SM_C2   58368             // 512
#define SM_IC   58880             // 512
#define SM_SCOL 59392             // 512
#define SM_FLAG 59904             // 4
#define SM_TOTAL 59912            // x3 CTAs = 179.7 KB

__device__ __forceinline__ uint32_t smem_u32(const void* p) {
    uint32_t a;
    asm("{ .reg .u64 t; cvta.to.shared.u64 t, %1; cvt.u32.u64 %0, t; }" : "=r"(a) : "l"(p));
    return a;
}
__device__ __forceinline__ uint32_t bf2u(__nv_bfloat162 h) {
    return *reinterpret_cast<uint32_t*>(&h);
}
__device__ __forceinline__ void ldsm4(uint32_t& r0, uint32_t& r1, uint32_t& r2, uint32_t& r3,
                                      uint32_t addr) {
    asm volatile("ldmatrix.sync.aligned.m8n8.x4.shared.b16 {%0,%1,%2,%3}, [%4];"
                 : "=r"(r0), "=r"(r1), "=r"(r2), "=r"(r3) : "r"(addr));
}
__device__ __forceinline__ void mma16816(float* c, const uint32_t* a, const uint32_t* b) {
    asm volatile(
        "mma.sync.aligned.m16n8k16.row.col.f32.bf16.bf16.f32 "
        "{%0,%1,%2,%3}, {%4,%5,%6,%7}, {%8,%9}, {%0,%1,%2,%3};"
        : "+f"(c[0]), "+f"(c[1]), "+f"(c[2]), "+f"(c[3])
        : "r"(a[0]), "r"(a[1]), "r"(a[2]), "r"(a[3]), "r"(b[0]), "r"(b[1]));
}
__device__ __forceinline__ float sqrt_ap(float v) {
    float r; asm("sqrt.approx.f32 %0, %1;" : "=f"(r) : "f"(v)); return r;
}
__device__ __forceinline__ float lg2_ap(float v) {
    float r; asm("lg2.approx.f32 %0, %1;" : "=f"(r) : "f"(v)); return r;
}
__device__ __forceinline__ float rcp_ap(float v) {
    float r; asm("rcp.approx.f32 %0, %1;" : "=f"(r) : "f"(v)); return r;
}
// d = dot, xc = x2+c2, R = 2*rcp(1-x2)*rcp(1-c2), lm = ln2*mask
// arg = 1 + sq*R >= 1 guaranteed (sq clamped >= 0, R > 0) -> no arg clamp needed
__device__ __forceinline__ float pdist(float d, float xc, float R, float lm) {
    float sq  = fmaxf(fmaf(d, -2.0f, xc), 0.0f);
    float arg = fmaf(sq, R, 1.0f);
    float v   = arg + sqrt_ap(fmaf(arg, arg, -1.0f));
    return lg2_ap(v) * lm;
}

__global__ void __launch_bounds__(TPB, 3)
dist_kernel(const float* __restrict__ x,
            const float* __restrict__ mask,
            const float* __restrict__ cw,
            float* __restrict__ out, int N, int ntiles) {
    extern __shared__ char smem[];
    const uint32_t sb = smem_u32(smem);
    const int tid = threadIdx.x, wid = tid >> 5, l = tid & 31;
    const int wr = wid & 1, wc = wid >> 1;    // warp grid 2 (rows) x 4 (cols)

    float* x2s  = (float*)(smem + SM_X2);
    float* ris  = (float*)(smem + SM_RIS);
    float* lms  = (float*)(smem + SM_LMS);
    float* ms   = (float*)(smem + SM_MS);
    float* c2s  = (float*)(smem + SM_C2);
    float* ics  = (float*)(smem + SM_IC);
    float* scol = (float*)(smem + SM_SCOL);
    float* px2  = (float*)(smem + SM_PX2);
    int*   flag = (int*)(smem + SM_FLAG);
    float* out_node = out + KC;

    // ---- inline centroid prep: 8 warps x 16 rows ----
#pragma unroll 2
    for (int r16 = 0; r16 < 16; r16++) {
        int row = wid * 16 + r16;
        float4 v = ((const float4*)(cw + (size_t)row * DD))[l];
        float ss = v.x * v.x + v.y * v.y + v.z * v.z + v.w * v.w;
#pragma unroll
        for (int o = 16; o; o >>= 1) ss += __shfl_xor_sync(0xffffffffu, ss, o);
        float norm = fmaxf(sqrtf(ss), 1e-5f);
        float s = tanhf(fminf(norm, 15.0f)) / norm;
        uint2 st;
        st.x = bf2u(__float22bfloat162_rn(make_float2(v.x * s, v.y * s)));
        st.y = bf2u(__float22bfloat162_rn(make_float2(v.z * s, v.w * s)));
        int c = l >> 1, half = l & 1;
        *(uint2*)(smem + SM_B + row * 256 + (((c ^ (row & 7)) << 4) | (half << 3))) = st;
        if (l == 0) {
            float c2 = ss * s * s;
            c2s[row] = c2;
            ics[row] = 2.0f / (1.0f - c2);
        }
    }
    if (tid < KC) scol[tid] = 0.0f;
    __syncthreads();

    const int a_row0 = wr * 32 + (l & 15);
    const int a_hi   = l >> 4;
    const int b_off  = ((l >> 4) << 3) + (l & 7);
    const int b_hi   = (l >> 3) & 1;

    float cs[8];
#pragma unroll
    for (int v = 0; v < 8; v++) cs[v] = 0.0f;
    float msacc = 0.0f;

    for (int tile = blockIdx.x; tile < ntiles; tile += NCTA) {
        const int tile0 = tile * TM;

        // ---- convert: LDG fp32 -> bf16 A tile (swizzled) + x2 partial STS ----
#pragma unroll
        for (int j = 0; j < 8; j++) {
            int i = tid + TPB * j;            // row = warp-uniform, c == lane
            int row = i >> 5, c = i & 31;
            int gr = tile0 + row; if (gr >= N) gr = N - 1;
            float4 v = ((const float4*)x)[(size_t)gr * 32 + c];
            px2[row * 32 + c] = v.x * v.x + v.y * v.y + v.z * v.z + v.w * v.w;
            uint2 st;
            st.x = bf2u(__float22bfloat162_rn(make_float2(v.x, v.y)));
            st.y = bf2u(__float22bfloat162_rn(make_float2(v.z, v.w)));
            *(uint2*)(smem + SM_A + row * 256 +
                      ((((c >> 1) ^ (row & 7)) << 4) | ((c & 1) << 3))) = st;
        }
        if (tid < TM) {
            int gr = tile0 + tid;
            float mv = (gr < N) ? mask[gr] : 0.0f;
            ms[tid] = mv;
            msacc += mv;
        }
        __syncthreads();

        // ---- phase 2: x2 row sums + per-row epilogue constants ----
        {
            int row = tid >> 2, q = tid & 3;
            const float4* pp = (const float4*)(smem + SM_PX2 + row * 128 + q * 32);
            float4 a = pp[0], b = pp[1];
            float s = ((a.x + a.y) + (a.z + a.w)) + ((b.x + b.y) + (b.z + b.w));
            s += __shfl_xor_sync(0xffffffffu, s, 1);
            s += __shfl_xor_sync(0xffffffffu, s, 2);
            if (q == 0) {
                x2s[row] = s;
                ris[row] = rcp_ap(1.0f - s);
                lms[row] = ms[row] * 0.69314718f;
            }
        }
        __syncthreads();

        // ---- two column passes: warp tile 32 rows x 16 cols ----
#pragma unroll 1
        for (int pass = 0; pass < 2; pass++) {
            float acc[2][2][4];
#pragma unroll
            for (int mi = 0; mi < 2; mi++)
#pragma unroll
                for (int t = 0; t < 2; t++)
#pragma unroll
                    for (int u = 0; u < 4; u++) acc[mi][t][u] = 0.0f;

            const int nrow = pass * 64 + wc * 16 + b_off;
            const uint32_t bd0 = sb + SM_B + nrow * 256;

#pragma unroll
            for (int kk = 0; kk < 8; kk++) {
                uint32_t af[2][4];
#pragma unroll
                for (int mi = 0; mi < 2; mi++) {
                    int row = a_row0 + mi * 16;
                    uint32_t ad = sb + SM_A + row * 256
                                + ((((kk << 1) | a_hi) ^ (row & 7)) << 4);
                    ldsm4(af[mi][0], af[mi][1], af[mi][2], af[mi][3], ad);
                }
                uint32_t bfr[2][2];
                {
                    uint32_t bdk = bd0 + ((((kk << 1) | b_hi) ^ (nrow & 7)) << 4);
                    uint32_t r0, r1, r2, r3;
                    ldsm4(r0, r1, r2, r3, bdk);
                    bfr[0][0] = r0; bfr[0][1] = r1;
                    bfr[1][0] = r2; bfr[1][1] = r3;
                }
#pragma unroll
                for (int mi = 0; mi < 2; mi++)
#pragma unroll
                    for (int t = 0; t < 2; t++) mma16816(acc[mi][t], af[mi], bfr[t]);
            }

            // epilogue: row constants via precomputed smem broadcasts
#pragma unroll
            for (int mi = 0; mi < 2; mi++) {
                int r0 = wr * 32 + mi * 16 + (l >> 2);
                int r1 = r0 + 8;
                float lm0 = lms[r0], lm1 = lms[r1];
                float x20 = x2s[r0], x21 = x2s[r1];
                float ri0 = ris[r0], ri1 = ris[r1];
                bool v0ok = (tile0 + r0) < N, v1ok = (tile0 + r1) < N;
                float* p0r = out_node + (size_t)(tile0 + r0) * KC;
                float* p1r = out_node + (size_t)(tile0 + r1) * KC;
#pragma unroll
                for (int t = 0; t < 2; t++) {
                    int col = pass * 64 + wc * 16 + t * 8 + ((l & 3) << 1);
                    float2 c2p = *(float2*)(c2s + col);
                    float2 icp = *(float2*)(ics + col);
                    float d0 = pdist(acc[mi][t][0], x20 + c2p.x, ri0 * icp.x, lm0);
                    float d1 = pdist(acc[mi][t][1], x20 + c2p.y, ri0 * icp.y, lm0);
                    float d2 = pdist(acc[mi][t][2], x21 + c2p.x, ri1 * icp.x, lm1);
                    float d3 = pdist(acc[mi][t][3], x21 + c2p.y, ri1 * icp.y, lm1);
                    if (v0ok) *(float2*)(p0r + col) = make_float2(d0, d1);
                    if (v1ok) *(float2*)(p1r + col) = make_float2(d2, d3);
                    cs[pass * 4 + t * 2]     += d0 + d2;
                    cs[pass * 4 + t * 2 + 1] += d1 + d3;
                }
            }
        }
        __syncthreads();   // protect A/px2/ms/x2s before next tile's convert
    }

    // ---- one-time column-sum reduction ----
#pragma unroll
    for (int v = 0; v < 8; v++) {
        float s = cs[v];
        s += __shfl_xor_sync(0xffffffffu, s, 4);
        s += __shfl_xor_sync(0xffffffffu, s, 8);
        s += __shfl_xor_sync(0xffffffffu, s, 16);
        if (l < 4) {
            int col = (v >> 2) * 64 + wc * 16 + ((v >> 1) & 1) * 8 + ((l & 3) << 1) + (v & 1);
            atomicAdd(&scol[col], s);
        }
    }
    {
        float wm = msacc;
#pragma unroll
        for (int o = 16; o; o >>= 1) wm += __shfl_xor_sync(0xffffffffu, wm, o);
        if (l == 0) atomicAdd(&g_masksum, wm);
    }
    __syncthreads();

    // ---- flush partials ----
    if (tid < KC) atomicAdd(&g_acc[tid], scol[tid]);
    __threadfence();
    __syncthreads();
    if (tid == 0) {
        int old = atomicAdd(&g_count, 1);
        *flag = (old == NCTA - 1) ? 1 : 0;
    }
    __syncthreads();
    if (*flag) {
        __threadfence();
        if (tid < KC) {
            float s  = atomicAdd(&g_acc[tid], 0.0f);      // coherent read
            float tm = atomicAdd(&g_masksum, 0.0f);
            out[tid] = s / tm;
        }
        __syncthreads();
        if (tid < KC) g_acc[tid] = 0.0f;                  // reset for next replay
        if (tid == 0) { g_masksum = 0.0f; atomicExch(&g_count, 0); }
    }
}

extern "C" void kernel_launch(void* const* d_in, const int* in_sizes, int n_in,
                              void* d_out, int out_size) {
    const float* x    = (const float*)d_in[0];
    const float* mask = (const float*)d_in[1];
    const float* cw   = (const float*)d_in[2];
    const int N = in_sizes[1];
    float* out = (float*)d_out;

    cudaFuncSetAttribute(dist_kernel, cudaFuncAttributeMaxDynamicSharedMemorySize, SM_TOTAL);
    const int ntiles = (N + TM - 1) / TM;
    dist_kernel<<<NCTA, TPB, SM_TOTAL>>>(x, mask, cw, out, N, ntiles);
}